// round 15
// baseline (speedup 1.0000x reference)
#include <cuda_runtime.h>
#include <cuda_bf16.h>
#include <cstdint>

// Problem constants
#define BATCH 2
#define SEQ   2049
#define SEQP  2112              // keys padded to 33*64 for fused attention
#define DMODEL 1024
#define HEADS 16
#define DHEAD 64
#define ROWS (BATCH*SEQ)        // 4098
#define QKV_COLS (3*HEADS*DHEAD) // 3072
#define NBH (BATCH*HEADS)       // 32
#define NKT 33                  // number of 64-key tiles

// ---------------------------------------------------------------------------
// Scratch (device globals; no allocation allowed)
// ---------------------------------------------------------------------------
__device__ float g_xn[ROWS * DMODEL];
__device__ float g_q[NBH * SEQ * DHEAD];
__device__ float g_k[NBH * SEQ * DHEAD];
__device__ float g_vT[NBH * DHEAD * SEQP];            // V transposed, padded keys
__device__ float g_attn[ROWS * DMODEL];
__device__ float g_wqkvT[QKV_COLS * DMODEL];
__device__ float g_woutT[DMODEL * DMODEL];

__device__ __forceinline__ float rtf32(float x) {
    uint32_t u;
    asm("cvt.rna.tf32.f32 %0, %1;" : "=r"(u) : "f"(x));
    return __uint_as_float(u);
}
__device__ __forceinline__ uint32_t f2u(float x) { return __float_as_uint(x); }
__device__ __forceinline__ float ex2(float x) {
    float y;
    asm("ex2.approx.f32 %0, %1;" : "=f"(y) : "f"(x));
    return y;
}
__device__ __forceinline__ uint32_t smem_u32(const void* p) {
    uint32_t a;
    asm("{ .reg .u64 t; cvta.to.shared.u64 t, %1; cvt.u32.u64 %0, t; }" : "=r"(a) : "l"(p));
    return a;
}
__device__ __forceinline__ void cp_async16(uint32_t dst, const void* src, int srcsize) {
    asm volatile("cp.async.cg.shared.global [%0], [%1], 16, %2;"
                 :: "r"(dst), "l"(src), "r"(srcsize));
}
#define CP_COMMIT() asm volatile("cp.async.commit_group;" ::: "memory")
#define CP_WAIT(n)  asm volatile("cp.async.wait_group %0;" :: "n"(n) : "memory")

#define MMA_TF32(acc, a0, a1, a2, a3, b0, b1)                                \
    asm volatile(                                                            \
        "mma.sync.aligned.m16n8k8.row.col.f32.tf32.tf32.f32 "                \
        "{%0,%1,%2,%3}, {%4,%5,%6,%7}, {%8,%9}, {%0,%1,%2,%3};\n"            \
        : "+f"((acc)[0]), "+f"((acc)[1]), "+f"((acc)[2]), "+f"((acc)[3])     \
        : "r"(a0), "r"(a1), "r"(a2), "r"(a3), "r"(b0), "r"(b1))

// ---------------------------------------------------------------------------
// Shared GEMM config: CTA tile 128x256, BK=32, 256 threads = 8 warps (2m x 4n),
// warp tile 64x64 (1.0 LDS/MMA). 3-stage cp.async pipeline.
// ---------------------------------------------------------------------------
#define GSTAGES 3
#define GSTAGE_FLOATS (128*32 + 256*32)                 // 12288
#define GEMM_SMEM_BYTES (GSTAGES * GSTAGE_FLOATS * 4)   // 147456

// Mainloop macro shared by both GEMM kernels (acc[4][8][4] must be in scope).
#define GEMM_MAINLOOP(Aptr, Bptr, Mv, Nv, Kv, ldav, ldbv)                     \
    const int KB = (Kv) >> 5;                                                 \
    auto issue_load = [&](int kb, int stage) {                                \
        const int k0 = kb << 5;                                               \
        const uint32_t sA = sb + (uint32_t)stage * (GSTAGE_FLOATS * 4);       \
        const uint32_t sB = sA + 128 * 32 * 4;                                \
        _Pragma("unroll")                                                     \
        for (int i = 0; i < 4; i++) {                                         \
            const int idx = tid + (i << 8);                                   \
            const int r  = idx >> 3;                                          \
            const int c4 = (idx & 7) << 2;                                    \
            const uint32_t off = (uint32_t)((r * 32 + (c4 ^ ((r & 7) << 2))) << 2); \
            cp_async16(sA + off, (Aptr) + (size_t)(row0 + r) * (ldav) + k0 + c4, \
                       (row0 + r < (Mv)) ? 16 : 0);                           \
        }                                                                     \
        _Pragma("unroll")                                                     \
        for (int i = 0; i < 8; i++) {                                         \
            const int idx = tid + (i << 8);                                   \
            const int r  = idx >> 3;                                          \
            const int c4 = (idx & 7) << 2;                                    \
            const uint32_t off = (uint32_t)((r * 32 + (c4 ^ ((r & 7) << 2))) << 2); \
            cp_async16(sB + off, (Bptr) + (size_t)(col0 + r) * (ldbv) + k0 + c4, \
                       (col0 + r < (Nv)) ? 16 : 0);                           \
        }                                                                     \
        CP_COMMIT();                                                          \
    };                                                                        \
    auto compute = [&](int stage) {                                           \
        const float* Ab = smem + stage * GSTAGE_FLOATS;                       \
        const float* Bb = Ab + 128 * 32;                                      \
        uint32_t af[2][4][4];                                                 \
        _Pragma("unroll")                                                     \
        for (int mt = 0; mt < 4; mt++) {                                      \
            const int r = (warp_m << 6) + (mt << 4) + g;                      \
            af[0][mt][0] = f2u(Ab[r * 32       + (tg ^ swz)]);                \
            af[0][mt][1] = f2u(Ab[(r + 8) * 32 + (tg ^ swz)]);                \
            af[0][mt][2] = f2u(Ab[r * 32       + ((tg + 4) ^ swz)]);          \
            af[0][mt][3] = f2u(Ab[(r + 8) * 32 + ((tg + 4) ^ swz)]);          \
        }                                                                     \
        _Pragma("unroll")                                                     \
        for (int kk = 0; kk < 4; kk++) {                                      \
            const int cur = kk & 1, nxt = cur ^ 1;                            \
            const int c = (kk << 3) + tg;                                     \
            uint32_t bf[8][2];                                                \
            _Pragma("unroll")                                                 \
            for (int nt = 0; nt < 8; nt++) {                                  \
                const int n = (warp_n << 6) + (nt << 3) + g;                  \
                bf[nt][0] = f2u(Bb[n * 32 + (c ^ swz)]);                      \
                bf[nt][1] = f2u(Bb[n * 32 + ((c + 4) ^ swz)]);                \
            }                                                                 \
            if (kk < 3) {                                                     \
                const int cn = ((kk + 1) << 3) + tg;                          \
                _Pragma("unroll")                                             \
                for (int mt = 0; mt < 4; mt++) {                              \
                    const int r = (warp_m << 6) + (mt << 4) + g;              \
                    af[nxt][mt][0] = f2u(Ab[r * 32       + (cn ^ swz)]);      \
                    af[nxt][mt][1] = f2u(Ab[(r + 8) * 32 + (cn ^ swz)]);      \
                    af[nxt][mt][2] = f2u(Ab[r * 32       + ((cn + 4) ^ swz)]);\
                    af[nxt][mt][3] = f2u(Ab[(r + 8) * 32 + ((cn + 4) ^ swz)]);\
                }                                                             \
            }                                                                 \
            _Pragma("unroll")                                                 \
            for (int mt = 0; mt < 4; mt++)                                    \
                _Pragma("unroll")                                             \
                for (int nt = 0; nt < 8; nt++)                                \
                    MMA_TF32(acc[mt][nt], af[cur][mt][0], af[cur][mt][1],     \
                             af[cur][mt][2], af[cur][mt][3], bf[nt][0], bf[nt][1]); \
        }                                                                     \
    };                                                                        \
    issue_load(0, 0);                                                         \
    if (KB > 1) issue_load(1, 1);                                             \
    for (int kb = 0; kb < KB; kb++) {                                         \
        const int st = kb % GSTAGES;                                          \
        if (kb + 1 < KB) { CP_WAIT(1); } else { CP_WAIT(0); }                 \
        __syncthreads();                                                      \
        if (kb + 2 < KB) issue_load(kb + 2, (kb + 2) % GSTAGES);              \
        compute(st);                                                          \
    }

// ---------------------------------------------------------------------------
// Plain GEMM: C = A @ B^T (used for the output projection)
// ---------------------------------------------------------------------------
__global__ __launch_bounds__(256, 1) void gemm_tf32_mma(
    const float* __restrict__ A, const float* __restrict__ B, float* __restrict__ C,
    int M, int N, int K, int lda, int ldb, int ldc)
{
    extern __shared__ float smem[];
    const uint32_t sb = smem_u32(smem);
    const int tid = threadIdx.x;
    const int lane = tid & 31, wid = tid >> 5;
    const int warp_m = wid >> 2, warp_n = wid & 3;
    const int g = lane >> 2, tg = lane & 3;
    const int swz = g << 2;
    const int row0 = blockIdx.y * 128;
    const int col0 = blockIdx.x * 256;

    float acc[4][8][4];
    #pragma unroll
    for (int mt = 0; mt < 4; mt++)
        #pragma unroll
        for (int nt = 0; nt < 8; nt++)
            #pragma unroll
            for (int i = 0; i < 4; i++) acc[mt][nt][i] = 0.f;

    GEMM_MAINLOOP(A, B, M, N, K, lda, ldb)

    #pragma unroll
    for (int mt = 0; mt < 4; mt++) {
        const int r = row0 + (warp_m << 6) + (mt << 4) + g;
        #pragma unroll
        for (int nt = 0; nt < 8; nt++) {
            const int cc = col0 + (warp_n << 6) + (nt << 3) + (tg << 1);
            if (r < M)
                *(float2*)(C + (size_t)r * ldc + cc) =
                    make_float2(acc[mt][nt][0], acc[mt][nt][1]);
            if (r + 8 < M)
                *(float2*)(C + (size_t)(r + 8) * ldc + cc) =
                    make_float2(acc[mt][nt][2], acc[mt][nt][3]);
        }
    }
}

// ---------------------------------------------------------------------------
// Fused QKV GEMM + RoPE + head reshape. Each warp's 64-col tile is exactly one
// head; rotate-half partner (i, i+32) lives in fragments nt and nt+4 of the
// SAME thread -> RoPE is thread-local in the epilogue.
// zone = col0/1024: 0 -> q (rotated), 1 -> k (rotated), 2 -> v (transposed).
// ---------------------------------------------------------------------------
__global__ __launch_bounds__(256, 1) void gemm_qkv_rope(
    const float* __restrict__ A, const float* __restrict__ B,
    float* __restrict__ gq, float* __restrict__ gk, float* __restrict__ gvT,
    int M, int K, int lda, int ldb)
{
    extern __shared__ float smem[];
    const uint32_t sb = smem_u32(smem);
    const int tid = threadIdx.x;
    const int lane = tid & 31, wid = tid >> 5;
    const int warp_m = wid >> 2, warp_n = wid & 3;
    const int g = lane >> 2, tg = lane & 3;
    const int swz = g << 2;
    const int row0 = blockIdx.y * 128;
    const int col0 = blockIdx.x * 256;

    float acc[4][8][4];
    #pragma unroll
    for (int mt = 0; mt < 4; mt++)
        #pragma unroll
        for (int nt = 0; nt < 8; nt++)
            #pragma unroll
            for (int i = 0; i < 4; i++) acc[mt][nt][i] = 0.f;

    GEMM_MAINLOOP(A, B, M, QKV_COLS, K, lda, ldb)

    // ---- epilogue: RoPE + reshape ----
    const int zone = col0 >> 10;                         // 0=q, 1=k, 2=v
    const int h = ((col0 & 1023) >> 6) + warp_n;         // head index
    float* qk = (zone == 0) ? gq : gk;

    #pragma unroll
    for (int mt = 0; mt < 4; mt++) {
        const int rbase = row0 + (warp_m << 6) + (mt << 4) + g;
        #pragma unroll
        for (int rs = 0; rs < 2; rs++) {
            const int r = rbase + (rs << 3);
            if (r >= M) continue;
            const int b = r / SEQ;
            const int n = r - b * SEQ;
            const int bh = b * HEADS + h;
            if (zone < 2) {
                float* dst = qk + ((size_t)bh * SEQ + n) * DHEAD;
                #pragma unroll
                for (int nt = 0; nt < 4; nt++) {
                    float o1[2], o2[2];
                    #pragma unroll
                    for (int j = 0; j < 2; j++) {
                        const int i = (nt << 3) + (tg << 1) + j;
                        float v1 = acc[mt][nt][(rs << 1) + j];
                        float v2 = acc[mt][nt + 4][(rs << 1) + j];
                        if (n > 0) {
                            float p = (float)(n - 1);
                            float invf = exp2f(-13.287712379549449f * ((float)i * (1.0f / 32.0f)));
                            float f = p * invf;
                            float c = cosf(f), s = sinf(f);
                            o1[j] = v1 * c - v2 * s;
                            o2[j] = v2 * c + v1 * s;
                        } else { o1[j] = v1; o2[j] = v2; }
                    }
                    const int i0 = (nt << 3) + (tg << 1);
                    *(float2*)(dst + i0)      = make_float2(rtf32(o1[0]), rtf32(o1[1]));
                    *(float2*)(dst + i0 + 32) = make_float2(rtf32(o2[0]), rtf32(o2[1]));
                }
            } else {
                // v: transposed scatter into vT [bh*64 + i][SEQP] at column n
                #pragma unroll
                for (int nt = 0; nt < 8; nt++) {
                    #pragma unroll
                    for (int j = 0; j < 2; j++) {
                        const int i = (nt << 3) + (tg << 1) + j;
                        gvT[((size_t)(bh * DHEAD + i)) * SEQP + n] =
                            rtf32(acc[mt][nt][(rs << 1) + j]);
                    }
                }
            }
        }
    }
}

// ---------------------------------------------------------------------------
// Fused flash attention (R13 configuration — measured best, unchanged).
// ---------------------------------------------------------------------------
#define ATT_SMEM_BYTES (17408 * 4)
#define QSCALE (0.125f * 1.4426950408889634f)   // SCALE * log2(e)

__global__ __launch_bounds__(128, 2) void fused_attn(
    const float* __restrict__ gq, const float* __restrict__ gk,
    const float* __restrict__ gvT, float* __restrict__ gattn)
{
    extern __shared__ float sm[];
    const uint32_t sb = smem_u32(sm);

    const int tid = threadIdx.x;
    const int lane = tid & 31, wid = tid >> 5;   // 4 warps
    const int g = lane >> 2, tg = lane & 3;
    const int m0 = wid << 5;                     // 32 query rows per warp
    const int qt = blockIdx.x, bh = blockIdx.y;
    const int q0 = qt * 128;
    const size_t qkBase = (size_t)bh * SEQ * DHEAD;
    const size_t vBase  = (size_t)bh * DHEAD * SEQP;
    const float4 z4 = make_float4(0.f, 0.f, 0.f, 0.f);

    #pragma unroll
    for (int i = 0; i < 16; i++) {
        const int idx = tid + (i << 7);
        const int r  = idx >> 4;
        const int c4 = (idx & 15) << 2;
        float4 v = (q0 + r < SEQ) ? *(const float4*)(gq + qkBase + (size_t)(q0 + r) * DHEAD + c4) : z4;
        *(float4*)(sm + r * 68 + c4) = v;
    }
    __syncthreads();
    uint32_t qf[2][8][4];
    #pragma unroll
    for (int mf = 0; mf < 2; mf++) {
        const int rb = m0 + (mf << 4);
        #pragma unroll
        for (int kk = 0; kk < 8; kk++) {
            const int c = (kk << 3) + tg;
            qf[mf][kk][0] = f2u(QSCALE * sm[(rb + g) * 68 + c]);
            qf[mf][kk][1] = f2u(QSCALE * sm[(rb + g + 8) * 68 + c]);
            qf[mf][kk][2] = f2u(QSCALE * sm[(rb + g) * 68 + c + 4]);
            qf[mf][kk][3] = f2u(QSCALE * sm[(rb + g + 8) * 68 + c + 4]);
        }
    }
    __syncthreads();

    auto issue_tile = [&](int kt, int buf) {
        const int key0 = kt * 64;
        const uint32_t sK = sb + (uint32_t)(buf * (4352 * 4));
        const uint32_t sV = sb + (uint32_t)((8704 + buf * 4352) * 4);
        #pragma unroll
        for (int i = 0; i < 8; i++) {
            const int idx = tid + (i << 7);
            const int r  = idx >> 4;
            const int c4 = (idx & 15) << 2;
            const uint32_t off = (uint32_t)((r * 68 + c4) << 2);
            cp_async16(sK + off, gk + qkBase + (size_t)(key0 + r) * DHEAD + c4,
                       (key0 + r < SEQ) ? 16 : 0);
            cp_async16(sV + off, gvT + vBase + (size_t)r * SEQP + key0 + c4, 16);
        }
        CP_COMMIT();
    };

    float oa[2][8][4];
    #pragma unroll
    for (int mf = 0; mf < 2; mf++)
        #pragma unroll
        for (int nt = 0; nt < 8; nt++)
            #pragma unroll
            for (int i = 0; i < 4; i++) oa[mf][nt][i] = 0.f;
    float rmA[2] = {-1e30f, -1e30f}, rmB[2] = {-1e30f, -1e30f};
    float rlA[2] = {0.f, 0.f}, rlB[2] = {0.f, 0.f};

    issue_tile(0, 0);

    for (int kt = 0; kt < NKT; kt++) {
        const int buf = kt & 1;
        const int key0 = kt * 64;
        CP_WAIT(0);
        __syncthreads();
        if (kt + 1 < NKT) issue_tile(kt + 1, buf ^ 1);
        const float* sK = sm + buf * 4352;
        const float* sV = sm + 8704 + buf * 4352;

        float sa[2][8][4];
        #pragma unroll
        for (int mf = 0; mf < 2; mf++)
            #pragma unroll
            for (int nt = 0; nt < 8; nt++)
                #pragma unroll
                for (int i = 0; i < 4; i++) sa[mf][nt][i] = 0.f;
        #pragma unroll
        for (int kk = 0; kk < 8; kk++) {
            const int c = (kk << 3) + tg;
            uint32_t b0 = f2u(sK[g * 68 + c]);
            uint32_t b1 = f2u(sK[g * 68 + c + 4]);
            #pragma unroll
            for (int nt = 0; nt < 8; nt++) {
                uint32_t n0 = 0, n1 = 0;
                if (nt < 7) {
                    n0 = f2u(sK[(((nt + 1) << 3) + g) * 68 + c]);
                    n1 = f2u(sK[(((nt + 1) << 3) + g) * 68 + c + 4]);
                }
                MMA_TF32(sa[0][nt], qf[0][kk][0], qf[0][kk][1], qf[0][kk][2], qf[0][kk][3], b0, b1);
                MMA_TF32(sa[1][nt], qf[1][kk][0], qf[1][kk][1], qf[1][kk][2], qf[1][kk][3], b0, b1);
                b0 = n0; b1 = n1;
            }
        }

        #pragma unroll
        for (int mf = 0; mf < 2; mf++) {
            float sm0 = -1e30f, sm1 = -1e30f;
            #pragma unroll
            for (int nt = 0; nt < 8; nt++) {
                const int kc = key0 + (nt << 3) + (tg << 1);
                if (kc >= SEQ)     { sa[mf][nt][0] = -1e30f; sa[mf][nt][2] = -1e30f; }
                if (kc + 1 >= SEQ) { sa[mf][nt][1] = -1e30f; sa[mf][nt][3] = -1e30f; }
                sm0 = fmaxf(sm0, fmaxf(sa[mf][nt][0], sa[mf][nt][1]));
                sm1 = fmaxf(sm1, fmaxf(sa[mf][nt][2], sa[mf][nt][3]));
            }
            sm0 = fmaxf(sm0, __shfl_xor_sync(0xFFFFFFFFu, sm0, 1));
            sm0 = fmaxf(sm0, __shfl_xor_sync(0xFFFFFFFFu, sm0, 2));
            sm1 = fmaxf(sm1, __shfl_xor_sync(0xFFFFFFFFu, sm1, 1));
            sm1 = fmaxf(sm1, __shfl_xor_sync(0xFFFFFFFFu, sm1, 2));
            const float nm0 = fmaxf(rmA[mf], sm0), nm1 = fmaxf(rmB[mf], sm1);
            const float c0 = ex2(rmA[mf] - nm0), c1 = ex2(rmB[mf] - nm1);
            rmA[mf] = nm0; rmB[mf] = nm1;
            float ls0 = 0.f, ls1 = 0.f;
            #pragma unroll
            for (int nt = 0; nt < 8; nt++) {
                sa[mf][nt][0] = ex2(sa[mf][nt][0] - nm0);
                sa[mf][nt][1] = ex2(sa[mf][nt][1] - nm0);
                sa[mf][nt][2] = ex2(sa[mf][nt][2] - nm1);
                sa[mf][nt][3] = ex2(sa[mf][nt][3] - nm1);
                ls0 += sa[mf][nt][0] + sa[mf][nt][1];
                ls1 += sa[mf][nt][2] + sa[mf][nt][3];
            }
            ls0 += __shfl_xor_sync(0xFFFFFFFFu, ls0, 1);
            ls0 += __shfl_xor_sync(0xFFFFFFFFu, ls0, 2);
            ls1 += __shfl_xor_sync(0xFFFFFFFFu, ls1, 1);
            ls1 += __shfl_xor_sync(0xFFFFFFFFu, ls1, 2);
            rlA[mf] = rlA[mf] * c0 + ls0;
            rlB[mf] = rlB[mf] * c1 + ls1;
            #pragma unroll
            for (int nt = 0; nt < 8; nt++) {
                oa[mf][nt][0] *= c0; oa[mf][nt][1] *= c0;
                oa[mf][nt][2] *= c1; oa[mf][nt][3] *= c1;
            }
        }

        const int srcA = (lane & 0x1C) | (tg >> 1);
        const int srcB = srcA | 2;
        const bool odd = (tg & 1) != 0;
        #pragma unroll
        for (int kk = 0; kk < 8; kk++) {
            uint32_t a[2][4];
            #pragma unroll
            for (int mf = 0; mf < 2; mf++) {
                float p0 = __shfl_sync(0xFFFFFFFFu, sa[mf][kk][0], srcA);
                float p1 = __shfl_sync(0xFFFFFFFFu, sa[mf][kk][1], srcA);
                float p2 = __shfl_sync(0xFFFFFFFFu, sa[mf][kk][2], srcA);
                float p3 = __shfl_sync(0xFFFFFFFFu, sa[mf][kk][3], srcA);
                float r0 = __shfl_sync(0xFFFFFFFFu, sa[mf][kk][0], srcB);
                float r1 = __shfl_sync(0xFFFFFFFFu, sa[mf][kk][1], srcB);
                float r2 = __shfl_sync(0xFFFFFFFFu, sa[mf][kk][2], srcB);
                float r3 = __shfl_sync(0xFFFFFFFFu, sa[mf][kk][3], srcB);
                a[mf][0] = f2u(rtf32(odd ? p1 : p0));
                a[mf][1] = f2u(rtf32(odd ? p3 : p2));
                a[mf][2] = f2u(rtf32(odd ? r1 : r0));
                a[mf][3] = f2u(rtf32(odd ? r3 : r2));
            }
            const int c = (kk << 3) + tg;
            uint32_t b0 = f2u(sV[g * 68 + c]);
            uint32_t b1 = f2u(sV[g * 68 + c + 4]);
            #pragma unroll
            for (int nt = 0; nt < 8; nt++) {
                uint32_t n0 = 0, n1 = 0;
                if (nt < 7) {
                    n0 = f2u(sV[(((nt + 1) << 3) + g) * 68 + c]);
                    n1 = f2u(sV[(((nt + 1) << 3) + g) * 68 + c + 4]);
                }
                MMA_TF32(oa[0][nt], a[0][0], a[0][1], a[0][2], a[0][3], b0, b1);
                MMA_TF32(oa[1][nt], a[1][0], a[1][1], a[1][2], a[1][3], b0, b1);
                b0 = n0; b1 = n1;
            }
        }
    }

    const int b = bh >> 4, h = bh & 15;
    #pragma unroll
    for (int mf = 0; mf < 2; mf++) {
        const float inv0 = 1.f / rlA[mf], inv1 = 1.f / rlB[mf];
        const int r0 = q0 + m0 + (mf << 4) + g, r1 = r0 + 8;
        #pragma unroll
        for (int nt = 0; nt < 8; nt++) {
            const int col = h * 64 + (nt << 3) + (tg << 1);
            if (r0 < SEQ)
                *(float2*)(gattn + (size_t)(b * SEQ + r0) * DMODEL + col) =
                    make_float2(oa[mf][nt][0] * inv0, oa[mf][nt][1] * inv0);
            if (r1 < SEQ)
                *(float2*)(gattn + (size_t)(b * SEQ + r1) * DMODEL + col) =
                    make_float2(oa[mf][nt][2] * inv1, oa[mf][nt][3] * inv1);
        }
    }
}

// ---------------------------------------------------------------------------
// LayerNorm (outputs tf32-rounded)
// ---------------------------------------------------------------------------
__global__ __launch_bounds__(256) void ln_kernel(
    const float* __restrict__ x, const float* __restrict__ gamma,
    const float* __restrict__ beta, float* __restrict__ xn)
{
    int row = blockIdx.x;
    int tid = threadIdx.x;
    const float4 v = ((const float4*)(x + (size_t)row * DMODEL))[tid];
    float s  = v.x + v.y + v.z + v.w;
    float ss = v.x*v.x + v.y*v.y + v.z*v.z + v.w*v.w;
    #pragma unroll
    for (int o = 16; o; o >>= 1) {
        s  += __shfl_xor_sync(0xFFFFFFFFu, s,  o);
        ss += __shfl_xor_sync(0xFFFFFFFFu, ss, o);
    }
    __shared__ float sm[8], sm2[8];
    int w = tid >> 5;
    if ((tid & 31) == 0) { sm[w] = s; sm2[w] = ss; }
    __syncthreads();
    float ts = 0.f, tss = 0.f;
    #pragma unroll
    for (int i = 0; i < 8; i++) { ts += sm[i]; tss += sm2[i]; }
    const float inv = 1.0f / DMODEL;
    float mu  = ts * inv;
    float var = tss * inv - mu * mu;
    float r = rsqrtf(var + 1e-5f);
    float4 gv = ((const float4*)gamma)[tid];
    float4 bv = ((const float4*)beta)[tid];
    float4 o;
    o.x = rtf32((v.x - mu) * r * gv.x + bv.x);
    o.y = rtf32((v.y - mu) * r * gv.y + bv.y);
    o.z = rtf32((v.z - mu) * r * gv.z + bv.z);
    o.w = rtf32((v.w - mu) * r * gv.w + bv.w);
    ((float4*)(xn + (size_t)row * DMODEL))[tid] = o;
}

// ---------------------------------------------------------------------------
// Transpose with tf32 rounding
// ---------------------------------------------------------------------------
__global__ __launch_bounds__(256) void transpose_rnd(
    const float* __restrict__ src, float* __restrict__ dst, int R, int C)
{
    __shared__ float t[32][33];
    int c0 = blockIdx.x * 32, r0 = blockIdx.y * 32;
    int x = threadIdx.x, y = threadIdx.y;
    #pragma unroll
    for (int i = 0; i < 32; i += 8) {
        int r = r0 + y + i, c = c0 + x;
        if (r < R && c < C) t[y + i][x] = src[(size_t)r * C + c];
    }
    __syncthreads();
    #pragma unroll
    for (int i = 0; i < 32; i += 8) {
        int r = c0 + y + i, c = r0 + x;
        if (r < C && c < R) dst[(size_t)r * R + c] = rtf32(t[x][y + i]);
    }
}

// Zero the key-padding columns of vT (cols SEQ..SEQP-1)
__global__ void vt_pad_zero(float* __restrict__ gvT)
{
    int idx = blockIdx.x * blockDim.x + threadIdx.x;
    const int padw = SEQP - SEQ;                 // 63
    const int total = NBH * DHEAD * padw;
    if (idx >= total) return;
    int c = idx % padw;
    int r = idx / padw;
    gvT[(size_t)r * SEQP + SEQ + c] = 0.f;
}

// ---------------------------------------------------------------------------
// Launch
// ---------------------------------------------------------------------------
static float* sym_addr(const void* sym) {
    void* p = nullptr;
    cudaGetSymbolAddress(&p, sym);
    return (float*)p;
}

extern "C" void kernel_launch(void* const* d_in, const int* in_sizes, int n_in,
                              void* d_out, int out_size)
{
    const float* x     = (const float*)d_in[0];
    const float* gamma = (const float*)d_in[1];
    const float* beta  = (const float*)d_in[2];
    const float* wqkv  = (const float*)d_in[3];
    const float* wout  = (const float*)d_in[4];
    float* out = (float*)d_out;

    float* xn    = sym_addr(g_xn);
    float* q     = sym_addr(g_q);
    float* k     = sym_addr(g_k);
    float* vT    = sym_addr(g_vT);
    float* attn  = sym_addr(g_attn);
    float* wqkvT = sym_addr(g_wqkvT);
    float* woutT = sym_addr(g_woutT);

    cudaFuncSetAttribute(gemm_tf32_mma, cudaFuncAttributeMaxDynamicSharedMemorySize, GEMM_SMEM_BYTES);
    cudaFuncSetAttribute(gemm_qkv_rope, cudaFuncAttributeMaxDynamicSharedMemorySize, GEMM_SMEM_BYTES);
    cudaFuncSetAttribute(fused_attn, cudaFuncAttributeMaxDynamicSharedMemorySize, ATT_SMEM_BYTES);

    // 1. LayerNorm + vT pad zero (independent)
    ln_kernel<<<ROWS, 256>>>(x, gamma, beta, xn);
    {
        int padtot = NBH * DHEAD * (SEQP - SEQ);
        vt_pad_zero<<<(padtot + 255) / 256, 256>>>(vT);
    }
    // 2. Transpose weights to [N,K] K-major (tf32-rounded)
    transpose_rnd<<<dim3(QKV_COLS / 32, DMODEL / 32), dim3(32, 8)>>>(wqkv, wqkvT, DMODEL, QKV_COLS);
    transpose_rnd<<<dim3(DMODEL / 32, DMODEL / 32), dim3(32, 8)>>>(wout, woutT, DMODEL, DMODEL);
    // 3. Fused QKV GEMM + RoPE + reshape -> q, k, vT
    gemm_qkv_rope<<<dim3(QKV_COLS / 256, (ROWS + 127) / 128), 256, GEMM_SMEM_BYTES>>>(
        xn, wqkvT, q, k, vT, ROWS, DMODEL, DMODEL, DMODEL);
    // 4. Fused flash attention -> attn [B*SEQ][DMODEL]
    fused_attn<<<dim3((SEQ + 127) / 128, NBH), 128, ATT_SMEM_BYTES>>>(q, k, vT, attn);
    // 5. out = attn @ w_out
    gemm_tf32_mma<<<dim3(DMODEL / 256, (ROWS + 127) / 128), 256, GEMM_SMEM_BYTES>>>(
        attn, woutT, out, ROWS, DMODEL, DMODEL, DMODEL, DMODEL, DMODEL);
}

// round 16
// speedup vs baseline: 1.1089x; 1.1089x over previous
#include <cuda_runtime.h>
#include <cuda_bf16.h>
#include <cstdint>

// Problem constants
#define BATCH 2
#define SEQ   2049
#define SEQP  2112              // keys padded to 33*64 for fused attention
#define DMODEL 1024
#define HEADS 16
#define DHEAD 64
#define ROWS (BATCH*SEQ)        // 4098
#define QKV_COLS (3*HEADS*DHEAD) // 3072
#define NBH (BATCH*HEADS)       // 32
#define NKT 33                  // number of 64-key tiles

// ---------------------------------------------------------------------------
// Scratch (device globals; no allocation allowed)
// ---------------------------------------------------------------------------
__device__ float g_xn[ROWS * DMODEL];
__device__ float g_qkv[ROWS * QKV_COLS];
__device__ float g_q[NBH * SEQ * DHEAD];
__device__ float g_k[NBH * SEQ * DHEAD];
__device__ float g_vT[NBH * DHEAD * SEQP];            // V transposed, padded keys
__device__ float g_attn[ROWS * DMODEL];
__device__ float g_wqkvT[QKV_COLS * DMODEL];
__device__ float g_woutT[DMODEL * DMODEL];

__device__ __forceinline__ float rtf32(float x) {
    uint32_t u;
    asm("cvt.rna.tf32.f32 %0, %1;" : "=r"(u) : "f"(x));
    return __uint_as_float(u);
}
__device__ __forceinline__ uint32_t f2u(float x) { return __float_as_uint(x); }
__device__ __forceinline__ float ex2(float x) {
    float y;
    asm("ex2.approx.f32 %0, %1;" : "=f"(y) : "f"(x));
    return y;
}
__device__ __forceinline__ uint32_t smem_u32(const void* p) {
    uint32_t a;
    asm("{ .reg .u64 t; cvta.to.shared.u64 t, %1; cvt.u32.u64 %0, t; }" : "=r"(a) : "l"(p));
    return a;
}
__device__ __forceinline__ void cp_async16(uint32_t dst, const void* src, int srcsize) {
    asm volatile("cp.async.cg.shared.global [%0], [%1], 16, %2;"
                 :: "r"(dst), "l"(src), "r"(srcsize));
}
#define CP_COMMIT() asm volatile("cp.async.commit_group;" ::: "memory")
#define CP_WAIT(n)  asm volatile("cp.async.wait_group %0;" :: "n"(n) : "memory")

#define MMA_TF32(acc, a0, a1, a2, a3, b0, b1)                                \
    asm volatile(                                                            \
        "mma.sync.aligned.m16n8k8.row.col.f32.tf32.tf32.f32 "                \
        "{%0,%1,%2,%3}, {%4,%5,%6,%7}, {%8,%9}, {%0,%1,%2,%3};\n"            \
        : "+f"((acc)[0]), "+f"((acc)[1]), "+f"((acc)[2]), "+f"((acc)[3])     \
        : "r"(a0), "r"(a1), "r"(a2), "r"(a3), "r"(b0), "r"(b1))

// ---------------------------------------------------------------------------
// tf32 warp-MMA GEMM: C = A[M,K] @ B[N,K]^T (both K-major). CTA tile 128x256,
// BK=32. 256 threads = 8 warps in 2(m) x 4(n); warp tile 64x64 (1.0 LDS/MMA).
// 4-stage cp.async pipeline, one barrier per k-block.
// N must be a multiple of 256, K multiple of 32. M guarded.
// ---------------------------------------------------------------------------
#define GSTAGES 4
#define GSTAGE_FLOATS (128*32 + 256*32)                 // 12288
#define GEMM_SMEM_BYTES (GSTAGES * GSTAGE_FLOATS * 4)   // 196608

__global__ __launch_bounds__(256, 1) void gemm_tf32_mma(
    const float* __restrict__ A, const float* __restrict__ B, float* __restrict__ C,
    int M, int N, int K, int lda, int ldb, int ldc)
{
    extern __shared__ float smem[];
    const uint32_t sb = smem_u32(smem);
    const int tid = threadIdx.x;
    const int lane = tid & 31, wid = tid >> 5;
    const int warp_m = wid >> 2;       // 0..1 (64 rows each)
    const int warp_n = wid & 3;        // 0..3 (64 cols each)
    const int g = lane >> 2, tg = lane & 3;
    const int swz = g << 2;
    const int row0 = blockIdx.y * 128;
    const int col0 = blockIdx.x * 256;

    float acc[4][8][4];
    #pragma unroll
    for (int mt = 0; mt < 4; mt++)
        #pragma unroll
        for (int nt = 0; nt < 8; nt++)
            #pragma unroll
            for (int i = 0; i < 4; i++) acc[mt][nt][i] = 0.f;

    const int KB = K >> 5;

    auto issue_load = [&](int kb, int stage) {
        const int k0 = kb << 5;
        const uint32_t sA = sb + (uint32_t)stage * (GSTAGE_FLOATS * 4);
        const uint32_t sB = sA + 128 * 32 * 4;
        #pragma unroll
        for (int i = 0; i < 4; i++) {                // A: 1024 float4
            const int idx = tid + (i << 8);
            const int r  = idx >> 3;                 // 0..127
            const int c4 = (idx & 7) << 2;
            const uint32_t off = (uint32_t)((r * 32 + (c4 ^ ((r & 7) << 2))) << 2);
            cp_async16(sA + off, A + (size_t)(row0 + r) * lda + k0 + c4,
                       (row0 + r < M) ? 16 : 0);
        }
        #pragma unroll
        for (int i = 0; i < 8; i++) {                // B: 2048 float4
            const int idx = tid + (i << 8);
            const int r  = idx >> 3;                 // 0..255
            const int c4 = (idx & 7) << 2;
            const uint32_t off = (uint32_t)((r * 32 + (c4 ^ ((r & 7) << 2))) << 2);
            cp_async16(sB + off, B + (size_t)(col0 + r) * ldb + k0 + c4,
                       (col0 + r < N) ? 16 : 0);
        }
        CP_COMMIT();
    };

    auto compute = [&](int stage) {
        const float* Ab = smem + stage * GSTAGE_FLOATS;
        const float* Bb = Ab + 128 * 32;
        uint32_t af[2][4][4];
        // prologue: A-fragments for kk=0
        #pragma unroll
        for (int mt = 0; mt < 4; mt++) {
            const int r = (warp_m << 6) + (mt << 4) + g;
            af[0][mt][0] = f2u(Ab[r * 32       + (tg ^ swz)]);
            af[0][mt][1] = f2u(Ab[(r + 8) * 32 + (tg ^ swz)]);
            af[0][mt][2] = f2u(Ab[r * 32       + ((tg + 4) ^ swz)]);
            af[0][mt][3] = f2u(Ab[(r + 8) * 32 + ((tg + 4) ^ swz)]);
        }
        #pragma unroll
        for (int kk = 0; kk < 4; kk++) {
            const int cur = kk & 1, nxt = cur ^ 1;
            const int c = (kk << 3) + tg;
            uint32_t bf[8][2];
            #pragma unroll
            for (int nt = 0; nt < 8; nt++) {
                const int n = (warp_n << 6) + (nt << 3) + g;
                bf[nt][0] = f2u(Bb[n * 32 + (c ^ swz)]);
                bf[nt][1] = f2u(Bb[n * 32 + ((c + 4) ^ swz)]);
            }
            if (kk < 3) {
                const int cn = ((kk + 1) << 3) + tg;
                #pragma unroll
                for (int mt = 0; mt < 4; mt++) {
                    const int r = (warp_m << 6) + (mt << 4) + g;
                    af[nxt][mt][0] = f2u(Ab[r * 32       + (cn ^ swz)]);
                    af[nxt][mt][1] = f2u(Ab[(r + 8) * 32 + (cn ^ swz)]);
                    af[nxt][mt][2] = f2u(Ab[r * 32       + ((cn + 4) ^ swz)]);
                    af[nxt][mt][3] = f2u(Ab[(r + 8) * 32 + ((cn + 4) ^ swz)]);
                }
            }
            #pragma unroll
            for (int mt = 0; mt < 4; mt++)
                #pragma unroll
                for (int nt = 0; nt < 8; nt++)
                    MMA_TF32(acc[mt][nt], af[cur][mt][0], af[cur][mt][1],
                             af[cur][mt][2], af[cur][mt][3], bf[nt][0], bf[nt][1]);
        }
    };

    issue_load(0, 0);
    if (KB > 1) issue_load(1, 1);
    if (KB > 2) issue_load(2, 2);

    for (int kb = 0; kb < KB; kb++) {
        const int st = kb % GSTAGES;
        if (kb + 1 < KB) { CP_WAIT(2); } else { CP_WAIT(0); }
        __syncthreads();
        if (kb + 3 < KB) issue_load(kb + 3, (kb + 3) % GSTAGES);
        compute(st);
    }

    #pragma unroll
    for (int mt = 0; mt < 4; mt++) {
        const int r = row0 + (warp_m << 6) + (mt << 4) + g;
        #pragma unroll
        for (int nt = 0; nt < 8; nt++) {
            const int cc = col0 + (warp_n << 6) + (nt << 3) + (tg << 1);
            if (r < M)
                *(float2*)(C + (size_t)r * ldc + cc) =
                    make_float2(acc[mt][nt][0], acc[mt][nt][1]);
            if (r + 8 < M)
                *(float2*)(C + (size_t)(r + 8) * ldc + cc) =
                    make_float2(acc[mt][nt][2], acc[mt][nt][3]);
        }
    }
}

// ---------------------------------------------------------------------------
// Fused flash attention (R13/R14 configuration — measured best, unchanged).
// Block = 128 queries x one (b,h). 128 threads = 4 warps; warp owns 32 query
// rows (2 m16 fragments) -> 1 LDS per 2 MMAs. cp.async double-buffered K/V;
// P via quad shuffles; base-2 softmax.
// ---------------------------------------------------------------------------
#define ATT_SMEM_BYTES (17408 * 4)
#define QSCALE (0.125f * 1.4426950408889634f)   // SCALE * log2(e)

__global__ __launch_bounds__(128, 2) void fused_attn(
    const float* __restrict__ gq, const float* __restrict__ gk,
    const float* __restrict__ gvT, float* __restrict__ gattn)
{
    extern __shared__ float sm[];
    const uint32_t sb = smem_u32(sm);

    const int tid = threadIdx.x;
    const int lane = tid & 31, wid = tid >> 5;   // 4 warps
    const int g = lane >> 2, tg = lane & 3;
    const int m0 = wid << 5;                     // 32 query rows per warp
    const int qt = blockIdx.x, bh = blockIdx.y;
    const int q0 = qt * 128;
    const size_t qkBase = (size_t)bh * SEQ * DHEAD;
    const size_t vBase  = (size_t)bh * DHEAD * SEQP;
    const float4 z4 = make_float4(0.f, 0.f, 0.f, 0.f);

    // ---- stage Q tile (overlaps K buffers; consumed before first tile) ----
    #pragma unroll
    for (int i = 0; i < 16; i++) {
        const int idx = tid + (i << 7);          // 0..2047 float4
        const int r  = idx >> 4;
        const int c4 = (idx & 15) << 2;
        float4 v = (q0 + r < SEQ) ? *(const float4*)(gq + qkBase + (size_t)(q0 + r) * DHEAD + c4) : z4;
        *(float4*)(sm + r * 68 + c4) = v;
    }
    __syncthreads();
    uint32_t qf[2][8][4];
    #pragma unroll
    for (int mf = 0; mf < 2; mf++) {
        const int rb = m0 + (mf << 4);
        #pragma unroll
        for (int kk = 0; kk < 8; kk++) {
            const int c = (kk << 3) + tg;
            qf[mf][kk][0] = f2u(QSCALE * sm[(rb + g) * 68 + c]);
            qf[mf][kk][1] = f2u(QSCALE * sm[(rb + g + 8) * 68 + c]);
            qf[mf][kk][2] = f2u(QSCALE * sm[(rb + g) * 68 + c + 4]);
            qf[mf][kk][3] = f2u(QSCALE * sm[(rb + g + 8) * 68 + c + 4]);
        }
    }
    __syncthreads();

    auto issue_tile = [&](int kt, int buf) {
        const int key0 = kt * 64;
        const uint32_t sK = sb + (uint32_t)(buf * (4352 * 4));
        const uint32_t sV = sb + (uint32_t)((8704 + buf * 4352) * 4);
        #pragma unroll
        for (int i = 0; i < 8; i++) {
            const int idx = tid + (i << 7);      // 0..1023
            const int r  = idx >> 4;             // 0..63
            const int c4 = (idx & 15) << 2;
            const uint32_t off = (uint32_t)((r * 68 + c4) << 2);
            cp_async16(sK + off, gk + qkBase + (size_t)(key0 + r) * DHEAD + c4,
                       (key0 + r < SEQ) ? 16 : 0);
            cp_async16(sV + off, gvT + vBase + (size_t)r * SEQP + key0 + c4, 16);
        }
        CP_COMMIT();
    };

    float oa[2][8][4];
    #pragma unroll
    for (int mf = 0; mf < 2; mf++)
        #pragma unroll
        for (int nt = 0; nt < 8; nt++)
            #pragma unroll
            for (int i = 0; i < 4; i++) oa[mf][nt][i] = 0.f;
    float rmA[2] = {-1e30f, -1e30f}, rmB[2] = {-1e30f, -1e30f};
    float rlA[2] = {0.f, 0.f}, rlB[2] = {0.f, 0.f};

    issue_tile(0, 0);

    for (int kt = 0; kt < NKT; kt++) {
        const int buf = kt & 1;
        const int key0 = kt * 64;
        CP_WAIT(0);
        __syncthreads();
        if (kt + 1 < NKT) issue_tile(kt + 1, buf ^ 1);
        const float* sK = sm + buf * 4352;
        const float* sV = sm + 8704 + buf * 4352;

        // ---- S' = (Q*scale*log2e) @ K^T, bf shared by both m-frags ----
        float sa[2][8][4];
        #pragma unroll
        for (int mf = 0; mf < 2; mf++)
            #pragma unroll
            for (int nt = 0; nt < 8; nt++)
                #pragma unroll
                for (int i = 0; i < 4; i++) sa[mf][nt][i] = 0.f;
        #pragma unroll
        for (int kk = 0; kk < 8; kk++) {
            const int c = (kk << 3) + tg;
            uint32_t b0 = f2u(sK[g * 68 + c]);
            uint32_t b1 = f2u(sK[g * 68 + c + 4]);
            #pragma unroll
            for (int nt = 0; nt < 8; nt++) {
                uint32_t n0 = 0, n1 = 0;
                if (nt < 7) {
                    n0 = f2u(sK[(((nt + 1) << 3) + g) * 68 + c]);
                    n1 = f2u(sK[(((nt + 1) << 3) + g) * 68 + c + 4]);
                }
                MMA_TF32(sa[0][nt], qf[0][kk][0], qf[0][kk][1], qf[0][kk][2], qf[0][kk][3], b0, b1);
                MMA_TF32(sa[1][nt], qf[1][kk][0], qf[1][kk][1], qf[1][kk][2], qf[1][kk][3], b0, b1);
                b0 = n0; b1 = n1;
            }
        }

        // ---- online softmax per m-frag (base-2 domain) ----
        #pragma unroll
        for (int mf = 0; mf < 2; mf++) {
            float sm0 = -1e30f, sm1 = -1e30f;
            #pragma unroll
            for (int nt = 0; nt < 8; nt++) {
                const int kc = key0 + (nt << 3) + (tg << 1);
                if (kc >= SEQ)     { sa[mf][nt][0] = -1e30f; sa[mf][nt][2] = -1e30f; }
                if (kc + 1 >= SEQ) { sa[mf][nt][1] = -1e30f; sa[mf][nt][3] = -1e30f; }
                sm0 = fmaxf(sm0, fmaxf(sa[mf][nt][0], sa[mf][nt][1]));
                sm1 = fmaxf(sm1, fmaxf(sa[mf][nt][2], sa[mf][nt][3]));
            }
            sm0 = fmaxf(sm0, __shfl_xor_sync(0xFFFFFFFFu, sm0, 1));
            sm0 = fmaxf(sm0, __shfl_xor_sync(0xFFFFFFFFu, sm0, 2));
            sm1 = fmaxf(sm1, __shfl_xor_sync(0xFFFFFFFFu, sm1, 1));
            sm1 = fmaxf(sm1, __shfl_xor_sync(0xFFFFFFFFu, sm1, 2));
            const float nm0 = fmaxf(rmA[mf], sm0), nm1 = fmaxf(rmB[mf], sm1);
            const float c0 = ex2(rmA[mf] - nm0), c1 = ex2(rmB[mf] - nm1);
            rmA[mf] = nm0; rmB[mf] = nm1;
            float ls0 = 0.f, ls1 = 0.f;
            #pragma unroll
            for (int nt = 0; nt < 8; nt++) {
                sa[mf][nt][0] = ex2(sa[mf][nt][0] - nm0);
                sa[mf][nt][1] = ex2(sa[mf][nt][1] - nm0);
                sa[mf][nt][2] = ex2(sa[mf][nt][2] - nm1);
                sa[mf][nt][3] = ex2(sa[mf][nt][3] - nm1);
                ls0 += sa[mf][nt][0] + sa[mf][nt][1];
                ls1 += sa[mf][nt][2] + sa[mf][nt][3];
            }
            ls0 += __shfl_xor_sync(0xFFFFFFFFu, ls0, 1);
            ls0 += __shfl_xor_sync(0xFFFFFFFFu, ls0, 2);
            ls1 += __shfl_xor_sync(0xFFFFFFFFu, ls1, 1);
            ls1 += __shfl_xor_sync(0xFFFFFFFFu, ls1, 2);
            rlA[mf] = rlA[mf] * c0 + ls0;
            rlB[mf] = rlB[mf] * c1 + ls1;
            #pragma unroll
            for (int nt = 0; nt < 8; nt++) {
                oa[mf][nt][0] *= c0; oa[mf][nt][1] *= c0;
                oa[mf][nt][2] *= c1; oa[mf][nt][3] *= c1;
            }
        }

        // ---- O += P @ V; P via quad shuffles; V bf shared by both m-frags ----
        const int srcA = (lane & 0x1C) | (tg >> 1);
        const int srcB = srcA | 2;
        const bool odd = (tg & 1) != 0;
        #pragma unroll
        for (int kk = 0; kk < 8; kk++) {
            uint32_t a[2][4];
            #pragma unroll
            for (int mf = 0; mf < 2; mf++) {
                float p0 = __shfl_sync(0xFFFFFFFFu, sa[mf][kk][0], srcA);
                float p1 = __shfl_sync(0xFFFFFFFFu, sa[mf][kk][1], srcA);
                float p2 = __shfl_sync(0xFFFFFFFFu, sa[mf][kk][2], srcA);
                float p3 = __shfl_sync(0xFFFFFFFFu, sa[mf][kk][3], srcA);
                float r0 = __shfl_sync(0xFFFFFFFFu, sa[mf][kk][0], srcB);
                float r1 = __shfl_sync(0xFFFFFFFFu, sa[mf][kk][1], srcB);
                float r2 = __shfl_sync(0xFFFFFFFFu, sa[mf][kk][2], srcB);
                float r3 = __shfl_sync(0xFFFFFFFFu, sa[mf][kk][3], srcB);
                a[mf][0] = f2u(rtf32(odd ? p1 : p0));
                a[mf][1] = f2u(rtf32(odd ? p3 : p2));
                a[mf][2] = f2u(rtf32(odd ? r1 : r0));
                a[mf][3] = f2u(rtf32(odd ? r3 : r2));
            }
            const int c = (kk << 3) + tg;
            uint32_t b0 = f2u(sV[g * 68 + c]);
            uint32_t b1 = f2u(sV[g * 68 + c + 4]);
            #pragma unroll
            for (int nt = 0; nt < 8; nt++) {
                uint32_t n0 = 0, n1 = 0;
                if (nt < 7) {
                    n0 = f2u(sV[(((nt + 1) << 3) + g) * 68 + c]);
                    n1 = f2u(sV[(((nt + 1) << 3) + g) * 68 + c + 4]);
                }
                MMA_TF32(oa[0][nt], a[0][0], a[0][1], a[0][2], a[0][3], b0, b1);
                MMA_TF32(oa[1][nt], a[1][0], a[1][1], a[1][2], a[1][3], b0, b1);
                b0 = n0; b1 = n1;
            }
        }
    }

    // ---- epilogue ----
    const int b = bh >> 4, h = bh & 15;
    #pragma unroll
    for (int mf = 0; mf < 2; mf++) {
        const float inv0 = 1.f / rlA[mf], inv1 = 1.f / rlB[mf];
        const int r0 = q0 + m0 + (mf << 4) + g, r1 = r0 + 8;
        #pragma unroll
        for (int nt = 0; nt < 8; nt++) {
            const int col = h * 64 + (nt << 3) + (tg << 1);
            if (r0 < SEQ)
                *(float2*)(gattn + (size_t)(b * SEQ + r0) * DMODEL + col) =
                    make_float2(oa[mf][nt][0] * inv0, oa[mf][nt][1] * inv0);
            if (r1 < SEQ)
                *(float2*)(gattn + (size_t)(b * SEQ + r1) * DMODEL + col) =
                    make_float2(oa[mf][nt][2] * inv1, oa[mf][nt][3] * inv1);
        }
    }
}

// ---------------------------------------------------------------------------
// LayerNorm (outputs tf32-rounded)
// ---------------------------------------------------------------------------
__global__ __launch_bounds__(256) void ln_kernel(
    const float* __restrict__ x, const float* __restrict__ gamma,
    const float* __restrict__ beta, float* __restrict__ xn)
{
    int row = blockIdx.x;
    int tid = threadIdx.x;
    const float4 v = ((const float4*)(x + (size_t)row * DMODEL))[tid];
    float s  = v.x + v.y + v.z + v.w;
    float ss = v.x*v.x + v.y*v.y + v.z*v.z + v.w*v.w;
    #pragma unroll
    for (int o = 16; o; o >>= 1) {
        s  += __shfl_xor_sync(0xFFFFFFFFu, s,  o);
        ss += __shfl_xor_sync(0xFFFFFFFFu, ss, o);
    }
    __shared__ float sm[8], sm2[8];
    int w = tid >> 5;
    if ((tid & 31) == 0) { sm[w] = s; sm2[w] = ss; }
    __syncthreads();
    float ts = 0.f, tss = 0.f;
    #pragma unroll
    for (int i = 0; i < 8; i++) { ts += sm[i]; tss += sm2[i]; }
    const float inv = 1.0f / DMODEL;
    float mu  = ts * inv;
    float var = tss * inv - mu * mu;
    float r = rsqrtf(var + 1e-5f);
    float4 gv = ((const float4*)gamma)[tid];
    float4 bv = ((const float4*)beta)[tid];
    float4 o;
    o.x = rtf32((v.x - mu) * r * gv.x + bv.x);
    o.y = rtf32((v.y - mu) * r * gv.y + bv.y);
    o.z = rtf32((v.z - mu) * r * gv.z + bv.z);
    o.w = rtf32((v.w - mu) * r * gv.w + bv.w);
    ((float4*)(xn + (size_t)row * DMODEL))[tid] = o;
}

// ---------------------------------------------------------------------------
// Transpose with tf32 rounding
// ---------------------------------------------------------------------------
__global__ __launch_bounds__(256) void transpose_rnd(
    const float* __restrict__ src, float* __restrict__ dst, int R, int C)
{
    __shared__ float t[32][33];
    int c0 = blockIdx.x * 32, r0 = blockIdx.y * 32;
    int x = threadIdx.x, y = threadIdx.y;
    #pragma unroll
    for (int i = 0; i < 32; i += 8) {
        int r = r0 + y + i, c = c0 + x;
        if (r < R && c < C) t[y + i][x] = src[(size_t)r * C + c];
    }
    __syncthreads();
    #pragma unroll
    for (int i = 0; i < 32; i += 8) {
        int r = c0 + y + i, c = r0 + x;
        if (r < C && c < R) dst[(size_t)r * R + c] = rtf32(t[x][y + i]);
    }
}

// ---------------------------------------------------------------------------
// RoPE + head reshape (also zeroes vT key-padding columns from low threads)
// ---------------------------------------------------------------------------
__global__ __launch_bounds__(256) void rope_reshape(
    const float* __restrict__ qkv, float* __restrict__ gq,
    float* __restrict__ gk, float* __restrict__ gvT)
{
    const int total = NBH * SEQ * 32;
    int idx = blockIdx.x * blockDim.x + threadIdx.x;
    if (idx >= total) return;

    const int padtot = NBH * DHEAD * (SEQP - SEQ);
    if (idx < padtot) {
        const int padw = SEQP - SEQ;             // 63
        int c = idx % padw;
        int r = idx / padw;
        gvT[(size_t)r * SEQP + SEQ + c] = 0.f;
    }

    int i = idx & 31;
    int t = idx >> 5;
    int n = t % SEQ; t /= SEQ;
    int h = t % HEADS;
    int b = t / HEADS;
    int bh = b * HEADS + h;

    const float* base = qkv + ((size_t)(b * SEQ + n)) * QKV_COLS + h * DHEAD;
    float q1 = base[i],        q2 = base[i + 32];
    float k1 = base[1024 + i], k2 = base[1024 + i + 32];
    float v1 = base[2048 + i], v2 = base[2048 + i + 32];
    float qo1 = q1, qo2 = q2, ko1 = k1, ko2 = k2;
    if (n > 0) {
        float p = (float)(n - 1);
        float invf = exp2f(-13.287712379549449f * ((float)i * (1.0f / 32.0f)));
        float f = p * invf;
        float c = cosf(f), s = sinf(f);
        qo1 = q1 * c - q2 * s;  qo2 = q2 * c + q1 * s;
        ko1 = k1 * c - k2 * s;  ko2 = k2 * c + k1 * s;
    }
    size_t dst = ((size_t)bh * SEQ + n) * DHEAD + i;
    gq[dst] = rtf32(qo1); gq[dst + 32] = rtf32(qo2);
    gk[dst] = rtf32(ko1); gk[dst + 32] = rtf32(ko2);
    size_t vd = ((size_t)bh * DHEAD + i) * SEQP + n;
    gvT[vd] = rtf32(v1); gvT[vd + (size_t)32 * SEQP] = rtf32(v2);
}

// ---------------------------------------------------------------------------
// Launch
// ---------------------------------------------------------------------------
static float* sym_addr(const void* sym) {
    void* p = nullptr;
    cudaGetSymbolAddress(&p, sym);
    return (float*)p;
}

extern "C" void kernel_launch(void* const* d_in, const int* in_sizes, int n_in,
                              void* d_out, int out_size)
{
    const float* x     = (const float*)d_in[0];
    const float* gamma = (const float*)d_in[1];
    const float* beta  = (const float*)d_in[2];
    const float* wqkv  = (const float*)d_in[3];
    const float* wout  = (const float*)d_in[4];
    float* out = (float*)d_out;

    float* xn    = sym_addr(g_xn);
    float* qkv   = sym_addr(g_qkv);
    float* q     = sym_addr(g_q);
    float* k     = sym_addr(g_k);
    float* vT    = sym_addr(g_vT);
    float* attn  = sym_addr(g_attn);
    float* wqkvT = sym_addr(g_wqkvT);
    float* woutT = sym_addr(g_woutT);

    cudaFuncSetAttribute(gemm_tf32_mma, cudaFuncAttributeMaxDynamicSharedMemorySize, GEMM_SMEM_BYTES);
    cudaFuncSetAttribute(fused_attn, cudaFuncAttributeMaxDynamicSharedMemorySize, ATT_SMEM_BYTES);

    // 1. LayerNorm (tf32-rounded)
    ln_kernel<<<ROWS, 256>>>(x, gamma, beta, xn);
    // 2. Transpose weights to [N,K] K-major (tf32-rounded)
    transpose_rnd<<<dim3(QKV_COLS / 32, DMODEL / 32), dim3(32, 8)>>>(wqkv, wqkvT, DMODEL, QKV_COLS);
    transpose_rnd<<<dim3(DMODEL / 32, DMODEL / 32), dim3(32, 8)>>>(wout, woutT, DMODEL, DMODEL);
    // 3. QKV = xn @ w_qkv  (N=3072 = 12 * 256)
    gemm_tf32_mma<<<dim3(QKV_COLS / 256, (ROWS + 127) / 128), 256, GEMM_SMEM_BYTES>>>(
        xn, wqkvT, qkv, ROWS, QKV_COLS, DMODEL, DMODEL, DMODEL, QKV_COLS);
    // 4. RoPE + reshape (q,k rounded; v transposed; pad zeroed inside)
    {
        int total = NBH * SEQ * 32;
        rope_reshape<<<(total + 255) / 256, 256>>>(qkv, q, k, vT);
    }
    // 5. Fused flash attention -> attn [B*SEQ][DMODEL]
    fused_attn<<<dim3((SEQ + 127) / 128, NBH), 128, ATT_SMEM_BYTES>>>(q, k, vT, attn);
    // 6. out = attn @ w_out  (N=1024 = 4 * 256)
    gemm_tf32_mma<<<dim3(DMODEL / 256, (ROWS + 127) / 128), 256, GEMM_SMEM_BYTES>>>(
        attn, woutT, out, ROWS, DMODEL, DMODEL, DMODEL, DMODEL, DMODEL);
}

// round 17
// speedup vs baseline: 1.1265x; 1.0159x over previous
#include <cuda_runtime.h>
#include <cuda_bf16.h>
#include <cstdint>

// Problem constants
#define BATCH 2
#define SEQ   2049
#define SEQP  2112              // keys padded to 33*64 for fused attention
#define DMODEL 1024
#define HEADS 16
#define DHEAD 64
#define ROWS (BATCH*SEQ)        // 4098
#define QKV_COLS (3*HEADS*DHEAD) // 3072
#define NBH (BATCH*HEADS)       // 32
#define NKT 33                  // number of 64-key tiles

// ---------------------------------------------------------------------------
// Scratch (device globals; no allocation allowed)
// ---------------------------------------------------------------------------
__device__ float g_xn[ROWS * DMODEL];
__device__ float g_qkv[ROWS * QKV_COLS];
__device__ float g_q[NBH * SEQ * DHEAD];
__device__ float g_k[NBH * SEQ * DHEAD];
__device__ float g_vT[NBH * DHEAD * SEQP];            // V transposed, padded keys
__device__ float g_attn[ROWS * DMODEL];
__device__ float g_wqkvT[QKV_COLS * DMODEL];
__device__ float g_woutT[DMODEL * DMODEL];

__device__ __forceinline__ float rtf32(float x) {
    uint32_t u;
    asm("cvt.rna.tf32.f32 %0, %1;" : "=r"(u) : "f"(x));
    return __uint_as_float(u);
}
__device__ __forceinline__ uint32_t f2u(float x) { return __float_as_uint(x); }
__device__ __forceinline__ float ex2(float x) {
    float y;
    asm("ex2.approx.f32 %0, %1;" : "=f"(y) : "f"(x));
    return y;
}
__device__ __forceinline__ uint32_t smem_u32(const void* p) {
    uint32_t a;
    asm("{ .reg .u64 t; cvta.to.shared.u64 t, %1; cvt.u32.u64 %0, t; }" : "=r"(a) : "l"(p));
    return a;
}
__device__ __forceinline__ void cp_async16(uint32_t dst, const void* src, int srcsize) {
    asm volatile("cp.async.cg.shared.global [%0], [%1], 16, %2;"
                 :: "r"(dst), "l"(src), "r"(srcsize));
}
#define CP_COMMIT() asm volatile("cp.async.commit_group;" ::: "memory")
#define CP_WAIT(n)  asm volatile("cp.async.wait_group %0;" :: "n"(n) : "memory")

#define MMA_TF32(acc, a0, a1, a2, a3, b0, b1)                                \
    asm volatile(                                                            \
        "mma.sync.aligned.m16n8k8.row.col.f32.tf32.tf32.f32 "                \
        "{%0,%1,%2,%3}, {%4,%5,%6,%7}, {%8,%9}, {%0,%1,%2,%3};\n"            \
        : "+f"((acc)[0]), "+f"((acc)[1]), "+f"((acc)[2]), "+f"((acc)[3])     \
        : "r"(a0), "r"(a1), "r"(a2), "r"(a3), "r"(b0), "r"(b1))

// ---------------------------------------------------------------------------
// tf32 warp-MMA GEMM: C = A[M,K] @ B[N,K]^T (both K-major). CTA tile 128x128,
// BK=32. 128 threads = 4 warps in 2(m) x 2(n); warp tile 64x64 (1.0 LDS/MMA).
// 2 CTAs/SM (independent barrier domains overlap load/compute phases).
// 3-stage cp.async pipeline, one barrier per k-block.
// N multiple of 128, K multiple of 32. M guarded.
// ---------------------------------------------------------------------------
#define GSTAGES 3
#define GSTAGE_FLOATS (128*32 + 128*32)                 // 8192
#define GEMM_SMEM_BYTES (GSTAGES * GSTAGE_FLOATS * 4)   // 98304

__global__ __launch_bounds__(128, 2) void gemm_tf32_mma(
    const float* __restrict__ A, const float* __restrict__ B, float* __restrict__ C,
    int M, int N, int K, int lda, int ldb, int ldc)
{
    extern __shared__ float smem[];
    const uint32_t sb = smem_u32(smem);
    const int tid = threadIdx.x;
    const int lane = tid & 31, wid = tid >> 5;   // 4 warps
    const int warp_m = wid >> 1;       // 0..1 (64 rows each)
    const int warp_n = wid & 1;        // 0..1 (64 cols each)
    const int g = lane >> 2, tg = lane & 3;
    const int swz = g << 2;
    const int row0 = blockIdx.y * 128;
    const int col0 = blockIdx.x * 128;

    float acc[4][8][4];
    #pragma unroll
    for (int mt = 0; mt < 4; mt++)
        #pragma unroll
        for (int nt = 0; nt < 8; nt++)
            #pragma unroll
            for (int i = 0; i < 4; i++) acc[mt][nt][i] = 0.f;

    const int KB = K >> 5;

    auto issue_load = [&](int kb, int stage) {
        const int k0 = kb << 5;
        const uint32_t sA = sb + (uint32_t)stage * (GSTAGE_FLOATS * 4);
        const uint32_t sB = sA + 128 * 32 * 4;
        #pragma unroll
        for (int i = 0; i < 8; i++) {                // A: 1024 float4
            const int idx = tid + (i << 7);
            const int r  = idx >> 3;                 // 0..127
            const int c4 = (idx & 7) << 2;
            const uint32_t off = (uint32_t)((r * 32 + (c4 ^ ((r & 7) << 2))) << 2);
            cp_async16(sA + off, A + (size_t)(row0 + r) * lda + k0 + c4,
                       (row0 + r < M) ? 16 : 0);
        }
        #pragma unroll
        for (int i = 0; i < 8; i++) {                // B: 1024 float4
            const int idx = tid + (i << 7);
            const int r  = idx >> 3;                 // 0..127
            const int c4 = (idx & 7) << 2;
            const uint32_t off = (uint32_t)((r * 32 + (c4 ^ ((r & 7) << 2))) << 2);
            cp_async16(sB + off, B + (size_t)(col0 + r) * ldb + k0 + c4,
                       (col0 + r < N) ? 16 : 0);
        }
        CP_COMMIT();
    };

    auto compute = [&](int stage) {
        const float* Ab = smem + stage * GSTAGE_FLOATS;
        const float* Bb = Ab + 128 * 32;
        uint32_t af[2][4][4];
        // prologue: A-fragments for kk=0
        #pragma unroll
        for (int mt = 0; mt < 4; mt++) {
            const int r = (warp_m << 6) + (mt << 4) + g;
            af[0][mt][0] = f2u(Ab[r * 32       + (tg ^ swz)]);
            af[0][mt][1] = f2u(Ab[(r + 8) * 32 + (tg ^ swz)]);
            af[0][mt][2] = f2u(Ab[r * 32       + ((tg + 4) ^ swz)]);
            af[0][mt][3] = f2u(Ab[(r + 8) * 32 + ((tg + 4) ^ swz)]);
        }
        #pragma unroll
        for (int kk = 0; kk < 4; kk++) {
            const int cur = kk & 1, nxt = cur ^ 1;
            const int c = (kk << 3) + tg;
            uint32_t bf[8][2];
            #pragma unroll
            for (int nt = 0; nt < 8; nt++) {
                const int n = (warp_n << 6) + (nt << 3) + g;
                bf[nt][0] = f2u(Bb[n * 32 + (c ^ swz)]);
                bf[nt][1] = f2u(Bb[n * 32 + ((c + 4) ^ swz)]);
            }
            if (kk < 3) {
                const int cn = ((kk + 1) << 3) + tg;
                #pragma unroll
                for (int mt = 0; mt < 4; mt++) {
                    const int r = (warp_m << 6) + (mt << 4) + g;
                    af[nxt][mt][0] = f2u(Ab[r * 32       + (cn ^ swz)]);
                    af[nxt][mt][1] = f2u(Ab[(r + 8) * 32 + (cn ^ swz)]);
                    af[nxt][mt][2] = f2u(Ab[r * 32       + ((cn + 4) ^ swz)]);
                    af[nxt][mt][3] = f2u(Ab[(r + 8) * 32 + ((cn + 4) ^ swz)]);
                }
            }
            #pragma unroll
            for (int mt = 0; mt < 4; mt++)
                #pragma unroll
                for (int nt = 0; nt < 8; nt++)
                    MMA_TF32(acc[mt][nt], af[cur][mt][0], af[cur][mt][1],
                             af[cur][mt][2], af[cur][mt][3], bf[nt][0], bf[nt][1]);
        }
    };

    issue_load(0, 0);
    if (KB > 1) issue_load(1, 1);

    for (int kb = 0; kb < KB; kb++) {
        const int st = kb % GSTAGES;
        if (kb + 1 < KB) { CP_WAIT(1); } else { CP_WAIT(0); }
        __syncthreads();
        if (kb + 2 < KB) issue_load(kb + 2, (kb + 2) % GSTAGES);
        compute(st);
    }

    #pragma unroll
    for (int mt = 0; mt < 4; mt++) {
        const int r = row0 + (warp_m << 6) + (mt << 4) + g;
        #pragma unroll
        for (int nt = 0; nt < 8; nt++) {
            const int cc = col0 + (warp_n << 6) + (nt << 3) + (tg << 1);
            if (r < M)
                *(float2*)(C + (size_t)r * ldc + cc) =
                    make_float2(acc[mt][nt][0], acc[mt][nt][1]);
            if (r + 8 < M)
                *(float2*)(C + (size_t)(r + 8) * ldc + cc) =
                    make_float2(acc[mt][nt][2], acc[mt][nt][3]);
        }
    }
}

// ---------------------------------------------------------------------------
// Fused flash attention (R13/R14 configuration — measured best, unchanged).
// ---------------------------------------------------------------------------
#define ATT_SMEM_BYTES (17408 * 4)
#define QSCALE (0.125f * 1.4426950408889634f)   // SCALE * log2(e)

__global__ __launch_bounds__(128, 2) void fused_attn(
    const float* __restrict__ gq, const float* __restrict__ gk,
    const float* __restrict__ gvT, float* __restrict__ gattn)
{
    extern __shared__ float sm[];
    const uint32_t sb = smem_u32(sm);

    const int tid = threadIdx.x;
    const int lane = tid & 31, wid = tid >> 5;   // 4 warps
    const int g = lane >> 2, tg = lane & 3;
    const int m0 = wid << 5;                     // 32 query rows per warp
    const int qt = blockIdx.x, bh = blockIdx.y;
    const int q0 = qt * 128;
    const size_t qkBase = (size_t)bh * SEQ * DHEAD;
    const size_t vBase  = (size_t)bh * DHEAD * SEQP;
    const float4 z4 = make_float4(0.f, 0.f, 0.f, 0.f);

    // ---- stage Q tile (overlaps K buffers; consumed before first tile) ----
    #pragma unroll
    for (int i = 0; i < 16; i++) {
        const int idx = tid + (i << 7);          // 0..2047 float4
        const int r  = idx >> 4;
        const int c4 = (idx & 15) << 2;
        float4 v = (q0 + r < SEQ) ? *(const float4*)(gq + qkBase + (size_t)(q0 + r) * DHEAD + c4) : z4;
        *(float4*)(sm + r * 68 + c4) = v;
    }
    __syncthreads();
    uint32_t qf[2][8][4];
    #pragma unroll
    for (int mf = 0; mf < 2; mf++) {
        const int rb = m0 + (mf << 4);
        #pragma unroll
        for (int kk = 0; kk < 8; kk++) {
            const int c = (kk << 3) + tg;
            qf[mf][kk][0] = f2u(QSCALE * sm[(rb + g) * 68 + c]);
            qf[mf][kk][1] = f2u(QSCALE * sm[(rb + g + 8) * 68 + c]);
            qf[mf][kk][2] = f2u(QSCALE * sm[(rb + g) * 68 + c + 4]);
            qf[mf][kk][3] = f2u(QSCALE * sm[(rb + g + 8) * 68 + c + 4]);
        }
    }
    __syncthreads();

    auto issue_tile = [&](int kt, int buf) {
        const int key0 = kt * 64;
        const uint32_t sK = sb + (uint32_t)(buf * (4352 * 4));
        const uint32_t sV = sb + (uint32_t)((8704 + buf * 4352) * 4);
        #pragma unroll
        for (int i = 0; i < 8; i++) {
            const int idx = tid + (i << 7);      // 0..1023
            const int r  = idx >> 4;             // 0..63
            const int c4 = (idx & 15) << 2;
            const uint32_t off = (uint32_t)((r * 68 + c4) << 2);
            cp_async16(sK + off, gk + qkBase + (size_t)(key0 + r) * DHEAD + c4,
                       (key0 + r < SEQ) ? 16 : 0);
            cp_async16(sV + off, gvT + vBase + (size_t)r * SEQP + key0 + c4, 16);
        }
        CP_COMMIT();
    };

    float oa[2][8][4];
    #pragma unroll
    for (int mf = 0; mf < 2; mf++)
        #pragma unroll
        for (int nt = 0; nt < 8; nt++)
            #pragma unroll
            for (int i = 0; i < 4; i++) oa[mf][nt][i] = 0.f;
    float rmA[2] = {-1e30f, -1e30f}, rmB[2] = {-1e30f, -1e30f};
    float rlA[2] = {0.f, 0.f}, rlB[2] = {0.f, 0.f};

    issue_tile(0, 0);

    for (int kt = 0; kt < NKT; kt++) {
        const int buf = kt & 1;
        const int key0 = kt * 64;
        CP_WAIT(0);
        __syncthreads();
        if (kt + 1 < NKT) issue_tile(kt + 1, buf ^ 1);
        const float* sK = sm + buf * 4352;
        const float* sV = sm + 8704 + buf * 4352;

        // ---- S' = (Q*scale*log2e) @ K^T, bf shared by both m-frags ----
        float sa[2][8][4];
        #pragma unroll
        for (int mf = 0; mf < 2; mf++)
            #pragma unroll
            for (int nt = 0; nt < 8; nt++)
                #pragma unroll
                for (int i = 0; i < 4; i++) sa[mf][nt][i] = 0.f;
        #pragma unroll
        for (int kk = 0; kk < 8; kk++) {
            const int c = (kk << 3) + tg;
            uint32_t b0 = f2u(sK[g * 68 + c]);
            uint32_t b1 = f2u(sK[g * 68 + c + 4]);
            #pragma unroll
            for (int nt = 0; nt < 8; nt++) {
                uint32_t n0 = 0, n1 = 0;
                if (nt < 7) {
                    n0 = f2u(sK[(((nt + 1) << 3) + g) * 68 + c]);
                    n1 = f2u(sK[(((nt + 1) << 3) + g) * 68 + c + 4]);
                }
                MMA_TF32(sa[0][nt], qf[0][kk][0], qf[0][kk][1], qf[0][kk][2], qf[0][kk][3], b0, b1);
                MMA_TF32(sa[1][nt], qf[1][kk][0], qf[1][kk][1], qf[1][kk][2], qf[1][kk][3], b0, b1);
                b0 = n0; b1 = n1;
            }
        }

        // ---- online softmax per m-frag (base-2 domain) ----
        #pragma unroll
        for (int mf = 0; mf < 2; mf++) {
            float sm0 = -1e30f, sm1 = -1e30f;
            #pragma unroll
            for (int nt = 0; nt < 8; nt++) {
                const int kc = key0 + (nt << 3) + (tg << 1);
                if (kc >= SEQ)     { sa[mf][nt][0] = -1e30f; sa[mf][nt][2] = -1e30f; }
                if (kc + 1 >= SEQ) { sa[mf][nt][1] = -1e30f; sa[mf][nt][3] = -1e30f; }
                sm0 = fmaxf(sm0, fmaxf(sa[mf][nt][0], sa[mf][nt][1]));
                sm1 = fmaxf(sm1, fmaxf(sa[mf][nt][2], sa[mf][nt][3]));
            }
            sm0 = fmaxf(sm0, __shfl_xor_sync(0xFFFFFFFFu, sm0, 1));
            sm0 = fmaxf(sm0, __shfl_xor_sync(0xFFFFFFFFu, sm0, 2));
            sm1 = fmaxf(sm1, __shfl_xor_sync(0xFFFFFFFFu, sm1, 1));
            sm1 = fmaxf(sm1, __shfl_xor_sync(0xFFFFFFFFu, sm1, 2));
            const float nm0 = fmaxf(rmA[mf], sm0), nm1 = fmaxf(rmB[mf], sm1);
            const float c0 = ex2(rmA[mf] - nm0), c1 = ex2(rmB[mf] - nm1);
            rmA[mf] = nm0; rmB[mf] = nm1;
            float ls0 = 0.f, ls1 = 0.f;
            #pragma unroll
            for (int nt = 0; nt < 8; nt++) {
                sa[mf][nt][0] = ex2(sa[mf][nt][0] - nm0);
                sa[mf][nt][1] = ex2(sa[mf][nt][1] - nm0);
                sa[mf][nt][2] = ex2(sa[mf][nt][2] - nm1);
                sa[mf][nt][3] = ex2(sa[mf][nt][3] - nm1);
                ls0 += sa[mf][nt][0] + sa[mf][nt][1];
                ls1 += sa[mf][nt][2] + sa[mf][nt][3];
            }
            ls0 += __shfl_xor_sync(0xFFFFFFFFu, ls0, 1);
            ls0 += __shfl_xor_sync(0xFFFFFFFFu, ls0, 2);
            ls1 += __shfl_xor_sync(0xFFFFFFFFu, ls1, 1);
            ls1 += __shfl_xor_sync(0xFFFFFFFFu, ls1, 2);
            rlA[mf] = rlA[mf] * c0 + ls0;
            rlB[mf] = rlB[mf] * c1 + ls1;
            #pragma unroll
            for (int nt = 0; nt < 8; nt++) {
                oa[mf][nt][0] *= c0; oa[mf][nt][1] *= c0;
                oa[mf][nt][2] *= c1; oa[mf][nt][3] *= c1;
            }
        }

        // ---- O += P @ V; P via quad shuffles; V bf shared by both m-frags ----
        const int srcA = (lane & 0x1C) | (tg >> 1);
        const int srcB = srcA | 2;
        const bool odd = (tg & 1) != 0;
        #pragma unroll
        for (int kk = 0; kk < 8; kk++) {
            uint32_t a[2][4];
            #pragma unroll
            for (int mf = 0; mf < 2; mf++) {
                float p0 = __shfl_sync(0xFFFFFFFFu, sa[mf][kk][0], srcA);
                float p1 = __shfl_sync(0xFFFFFFFFu, sa[mf][kk][1], srcA);
                float p2 = __shfl_sync(0xFFFFFFFFu, sa[mf][kk][2], srcA);
                float p3 = __shfl_sync(0xFFFFFFFFu, sa[mf][kk][3], srcA);
                float r0 = __shfl_sync(0xFFFFFFFFu, sa[mf][kk][0], srcB);
                float r1 = __shfl_sync(0xFFFFFFFFu, sa[mf][kk][1], srcB);
                float r2 = __shfl_sync(0xFFFFFFFFu, sa[mf][kk][2], srcB);
                float r3 = __shfl_sync(0xFFFFFFFFu, sa[mf][kk][3], srcB);
                a[mf][0] = f2u(rtf32(odd ? p1 : p0));
                a[mf][1] = f2u(rtf32(odd ? p3 : p2));
                a[mf][2] = f2u(rtf32(odd ? r1 : r0));
                a[mf][3] = f2u(rtf32(odd ? r3 : r2));
            }
            const int c = (kk << 3) + tg;
            uint32_t b0 = f2u(sV[g * 68 + c]);
            uint32_t b1 = f2u(sV[g * 68 + c + 4]);
            #pragma unroll
            for (int nt = 0; nt < 8; nt++) {
                uint32_t n0 = 0, n1 = 0;
                if (nt < 7) {
                    n0 = f2u(sV[(((nt + 1) << 3) + g) * 68 + c]);
                    n1 = f2u(sV[(((nt + 1) << 3) + g) * 68 + c + 4]);
                }
                MMA_TF32(oa[0][nt], a[0][0], a[0][1], a[0][2], a[0][3], b0, b1);
                MMA_TF32(oa[1][nt], a[1][0], a[1][1], a[1][2], a[1][3], b0, b1);
                b0 = n0; b1 = n1;
            }
        }
    }

    // ---- epilogue ----
    const int b = bh >> 4, h = bh & 15;
    #pragma unroll
    for (int mf = 0; mf < 2; mf++) {
        const float inv0 = 1.f / rlA[mf], inv1 = 1.f / rlB[mf];
        const int r0 = q0 + m0 + (mf << 4) + g, r1 = r0 + 8;
        #pragma unroll
        for (int nt = 0; nt < 8; nt++) {
            const int col = h * 64 + (nt << 3) + (tg << 1);
            if (r0 < SEQ)
                *(float2*)(gattn + (size_t)(b * SEQ + r0) * DMODEL + col) =
                    make_float2(oa[mf][nt][0] * inv0, oa[mf][nt][1] * inv0);
            if (r1 < SEQ)
                *(float2*)(gattn + (size_t)(b * SEQ + r1) * DMODEL + col) =
                    make_float2(oa[mf][nt][2] * inv1, oa[mf][nt][3] * inv1);
        }
    }
}

// ---------------------------------------------------------------------------
// LayerNorm (outputs tf32-rounded)
// ---------------------------------------------------------------------------
__global__ __launch_bounds__(256) void ln_kernel(
    const float* __restrict__ x, const float* __restrict__ gamma,
    const float* __restrict__ beta, float* __restrict__ xn)
{
    int row = blockIdx.x;
    int tid = threadIdx.x;
    const float4 v = ((const float4*)(x + (size_t)row * DMODEL))[tid];
    float s  = v.x + v.y + v.z + v.w;
    float ss = v.x*v.x + v.y*v.y + v.z*v.z + v.w*v.w;
    #pragma unroll
    for (int o = 16; o; o >>= 1) {
        s  += __shfl_xor_sync(0xFFFFFFFFu, s,  o);
        ss += __shfl_xor_sync(0xFFFFFFFFu, ss, o);
    }
    __shared__ float sm[8], sm2[8];
    int w = tid >> 5;
    if ((tid & 31) == 0) { sm[w] = s; sm2[w] = ss; }
    __syncthreads();
    float ts = 0.f, tss = 0.f;
    #pragma unroll
    for (int i = 0; i < 8; i++) { ts += sm[i]; tss += sm2[i]; }
    const float inv = 1.0f / DMODEL;
    float mu  = ts * inv;
    float var = tss * inv - mu * mu;
    float r = rsqrtf(var + 1e-5f);
    float4 gv = ((const float4*)gamma)[tid];
    float4 bv = ((const float4*)beta)[tid];
    float4 o;
    o.x = rtf32((v.x - mu) * r * gv.x + bv.x);
    o.y = rtf32((v.y - mu) * r * gv.y + bv.y);
    o.z = rtf32((v.z - mu) * r * gv.z + bv.z);
    o.w = rtf32((v.w - mu) * r * gv.w + bv.w);
    ((float4*)(xn + (size_t)row * DMODEL))[tid] = o;
}

// ---------------------------------------------------------------------------
// Transpose with tf32 rounding
// ---------------------------------------------------------------------------
__global__ __launch_bounds__(256) void transpose_rnd(
    const float* __restrict__ src, float* __restrict__ dst, int R, int C)
{
    __shared__ float t[32][33];
    int c0 = blockIdx.x * 32, r0 = blockIdx.y * 32;
    int x = threadIdx.x, y = threadIdx.y;
    #pragma unroll
    for (int i = 0; i < 32; i += 8) {
        int r = r0 + y + i, c = c0 + x;
        if (r < R && c < C) t[y + i][x] = src[(size_t)r * C + c];
    }
    __syncthreads();
    #pragma unroll
    for (int i = 0; i < 32; i += 8) {
        int r = c0 + y + i, c = r0 + x;
        if (r < C && c < R) dst[(size_t)r * R + c] = rtf32(t[x][y + i]);
    }
}

// ---------------------------------------------------------------------------
// RoPE + head reshape (also zeroes vT key-padding columns from low threads)
// ---------------------------------------------------------------------------
__global__ __launch_bounds__(256) void rope_reshape(
    const float* __restrict__ qkv, float* __restrict__ gq,
    float* __restrict__ gk, float* __restrict__ gvT)
{
    const int total = NBH * SEQ * 32;
    int idx = blockIdx.x * blockDim.x + threadIdx.x;
    if (idx >= total) return;

    const int padtot = NBH * DHEAD * (SEQP - SEQ);
    if (idx < padtot) {
        const int padw = SEQP - SEQ;             // 63
        int c = idx % padw;
        int r = idx / padw;
        gvT[(size_t)r * SEQP + SEQ + c] = 0.f;
    }

    int i = idx & 31;
    int t = idx >> 5;
    int n = t % SEQ; t /= SEQ;
    int h = t % HEADS;
    int b = t / HEADS;
    int bh = b * HEADS + h;

    const float* base = qkv + ((size_t)(b * SEQ + n)) * QKV_COLS + h * DHEAD;
    float q1 = base[i],        q2 = base[i + 32];
    float k1 = base[1024 + i], k2 = base[1024 + i + 32];
    float v1 = base[2048 + i], v2 = base[2048 + i + 32];
    float qo1 = q1, qo2 = q2, ko1 = k1, ko2 = k2;
    if (n > 0) {
        float p = (float)(n - 1);
        float invf = exp2f(-13.287712379549449f * ((float)i * (1.0f / 32.0f)));
        float f = p * invf;
        float c = cosf(f), s = sinf(f);
        qo1 = q1 * c - q2 * s;  qo2 = q2 * c + q1 * s;
        ko1 = k1 * c - k2 * s;  ko2 = k2 * c + k1 * s;
    }
    size_t dst = ((size_t)bh * SEQ + n) * DHEAD + i;
    gq[dst] = rtf32(qo1); gq[dst + 32] = rtf32(qo2);
    gk[dst] = rtf32(ko1); gk[dst + 32] = rtf32(ko2);
    size_t vd = ((size_t)bh * DHEAD + i) * SEQP + n;
    gvT[vd] = rtf32(v1); gvT[vd + (size_t)32 * SEQP] = rtf32(v2);
}

// ---------------------------------------------------------------------------
// Launch
// ---------------------------------------------------------------------------
static float* sym_addr(const void* sym) {
    void* p = nullptr;
    cudaGetSymbolAddress(&p, sym);
    return (float*)p;
}

extern "C" void kernel_launch(void* const* d_in, const int* in_sizes, int n_in,
                              void* d_out, int out_size)
{
    const float* x     = (const float*)d_in[0];
    const float* gamma = (const float*)d_in[1];
    const float* beta  = (const float*)d_in[2];
    const float* wqkv  = (const float*)d_in[3];
    const float* wout  = (const float*)d_in[4];
    float* out = (float*)d_out;

    float* xn    = sym_addr(g_xn);
    float* qkv   = sym_addr(g_qkv);
    float* q     = sym_addr(g_q);
    float* k     = sym_addr(g_k);
    float* vT    = sym_addr(g_vT);
    float* attn  = sym_addr(g_attn);
    float* wqkvT = sym_addr(g_wqkvT);
    float* woutT = sym_addr(g_woutT);

    cudaFuncSetAttribute(gemm_tf32_mma, cudaFuncAttributeMaxDynamicSharedMemorySize, GEMM_SMEM_BYTES);
    cudaFuncSetAttribute(fused_attn, cudaFuncAttributeMaxDynamicSharedMemorySize, ATT_SMEM_BYTES);

    // 1. LayerNorm (tf32-rounded)
    ln_kernel<<<ROWS, 256>>>(x, gamma, beta, xn);
    // 2. Transpose weights to [N,K] K-major (tf32-rounded)
    transpose_rnd<<<dim3(QKV_COLS / 32, DMODEL / 32), dim3(32, 8)>>>(wqkv, wqkvT, DMODEL, QKV_COLS);
    transpose_rnd<<<dim3(DMODEL / 32, DMODEL / 32), dim3(32, 8)>>>(wout, woutT, DMODEL, DMODEL);
    // 3. QKV = xn @ w_qkv
    gemm_tf32_mma<<<dim3(QKV_COLS / 128, (ROWS + 127) / 128), 128, GEMM_SMEM_BYTES>>>(
        xn, wqkvT, qkv, ROWS, QKV_COLS, DMODEL, DMODEL, DMODEL, QKV_COLS);
    // 4. RoPE + reshape (q,k rounded; v transposed; pad zeroed inside)
    {
        int total = NBH * SEQ * 32;
        rope_reshape<<<(total + 255) / 256, 256>>>(qkv, q, k, vT);
    }
    // 5. Fused flash attention -> attn [B*SEQ][DMODEL]
    fused_attn<<<dim3((SEQ + 127) / 128, NBH), 128, ATT_SMEM_BYTES>>>(q, k, vT, attn);
    // 6. out = attn @ w_out
    gemm_tf32_mma<<<dim3(DMODEL / 128, (ROWS + 127) / 128), 128, GEMM_SMEM_BYTES>>>(
        attn, woutT, out, ROWS, DMODEL, DMODEL, DMODEL, DMODEL, DMODEL);
}